// round 9
// baseline (speedup 1.0000x reference)
#include <cuda_runtime.h>
#include <cstdint>

// ---------------- problem constants ----------------
#define NN      50000
#define EMAX    800000
#define F_IN    500
#define H1      8
#define C1      16
#define HC      128        // H1*C1
#define NC      7
#define NEG     0.2f

// ---------------- device scratch (no allocations allowed) ----------------
// 256B-aligned: these are accessed with float4 loads/stores.
__device__ __align__(256) float g_h1[(size_t)NN * HC];    // layer1 pre-agg features
__device__ __align__(256) float g_out1[(size_t)NN * HC];  // layer1 output (relu+bias)
__device__ float g_asrc1[NN * H1];
__device__ float g_adst1[NN * H1];
__device__ __align__(256) float g_h2[(size_t)NN * NC];
__device__ float g_asrc2[NN];
__device__ float g_adst2[NN];
__device__ int   g_deg[NN];
__device__ int   g_offs[NN + 1];
__device__ int   g_cursor[NN];
__device__ int   g_csr[EMAX];                  // src node per edge, grouped by dst
__device__ int   g_src[EMAX];                  // decoded edge endpoints
__device__ int   g_dst[EMAX];
__device__ int   g_is64;                       // 1 if edge_index is int64

// ---------------- f32x2 helpers (FFMA2: 2x fp32 throughput, PTX-only) -----
__device__ __forceinline__ unsigned long long pack2(float lo, float hi) {
    unsigned long long r;
    asm("mov.b64 %0, {%1, %2};" : "=l"(r) : "f"(lo), "f"(hi));
    return r;
}
__device__ __forceinline__ void ffma2(unsigned long long& acc,
                                      unsigned long long a,
                                      unsigned long long b) {
    asm("fma.rn.f32x2 %0, %1, %2, %0;" : "+l"(acc) : "l"(a), "l"(b));
}
__device__ __forceinline__ float2 unpack2(unsigned long long v) {
    float lo, hi;
    asm("mov.b64 {%0, %1}, %2;" : "=f"(lo), "=f"(hi) : "l"(v));
    return make_float2(lo, hi);
}

__device__ __forceinline__ float lrelu(float v) {
    return (v > 0.f) ? v : NEG * v;
}

// =====================================================================
// Edge-index dtype detection (int32 vs int64, decided on-device).
// int64 little-endian with node ids < 2^31 => every odd int32 word is 0.
// For int32 data the odd words are random node ids: P(all 32 zero) ~ 0.
// =====================================================================
__global__ void k_detect(const int* __restrict__ ei32) {
    int lane = threadIdx.x;                 // 32 threads
    int v = ei32[2 * lane + 1];             // odd words of first 64 ints
    unsigned nz = __ballot_sync(0xffffffffu, v != 0);
    if (lane == 0) g_is64 = (nz == 0u) ? 1 : 0;
}

__global__ void k_zero() {
    int i = blockIdx.x * blockDim.x + threadIdx.x;
    if (i < NN) g_deg[i] = 0;
}

// decode + degree histogram fused (g_deg must be zeroed beforehand)
__global__ void k_decode(const void* __restrict__ ei, int E) {
    int i = blockIdx.x * blockDim.x + threadIdx.x;
    if (i >= E) return;
    int s, d;
    if (g_is64) {
        const long long* p = (const long long*)ei;
        s = (int)p[i];
        d = (int)p[E + i];
    } else {
        const int* p = (const int*)ei;
        s = p[i];
        d = p[E + i];
    }
    // clamp: a mis-detection must not trap (finite wrong answer > crash)
    s = min(max(s, 0), NN - 1);
    d = min(max(d, 0), NN - 1);
    g_src[i] = s;
    g_dst[i] = d;
    atomicAdd(&g_deg[d], 1);
}

// =====================================================================
// GEMM1: h1 = x[50000,500] @ W1[500,128]     (fp32, FFMA2 inner loop)
// Block tile 128x128, BK=20 (500 = 25*20), 256 threads, 8x8 per thread.
// Software pipeline via registers; As stored K-MAJOR ([BK][BMP=132]);
// inner loop 4x LDS.128 + 32 FFMA2 per kk; fused attention-logit epilogue.
// =====================================================================
#define BM 128
#define BN 128
#define BK 20
#define BMP 132   // As row stride (K-major): 132*4B = 528B, 16B-aligned rows
#define NKT (F_IN / BK)   // 25 k-tiles

__global__ __launch_bounds__(256, 2)
void k_gemm1(const float* __restrict__ x, const float* __restrict__ W,
             const float* __restrict__ att_src, const float* __restrict__ att_dst) {
    __shared__ __align__(16) float As[BK * BMP];    // [20][132] K-major
    __shared__ __align__(16) float Bs[BK * BN];     // [20][128]

    const int tid = threadIdx.x;
    const int tx = tid & 15;          // 16 col groups * 8 cols
    const int ty = tid >> 4;          // 16 row groups * 8 rows
    const int row0 = blockIdx.x * BM;

    unsigned long long acc[8][4];
#pragma unroll
    for (int i = 0; i < 8; i++)
#pragma unroll
        for (int j = 0; j < 4; j++) acc[i][j] = 0ULL;

    float2 pf[10];                    // prefetch regs: 5x A, 5x B

    // ---- prefetch tile 0 ----
#pragma unroll
    for (int j = 0; j < 5; j++) {
        int idx = tid + j * 256;      // 0..1279 over A tile
        int r = idx / 10, c2 = (idx % 10) * 2;
        int gr = row0 + r;
        float2 v = make_float2(0.f, 0.f);
        if (gr < NN) v = *(const float2*)(x + (size_t)gr * F_IN + c2);
        pf[j] = v;
    }
#pragma unroll
    for (int j = 0; j < 5; j++) {
        int bi = tid + j * 256;       // 0..1279 over B tile
        int r = bi >> 6, c2 = (bi & 63) * 2;
        pf[5 + j] = *(const float2*)(W + (size_t)r * BN + c2);
    }

    for (int kt = 0; kt < NKT; kt++) {
        // ---- store prefetched tile to smem (A transposed to K-major) ----
#pragma unroll
        for (int j = 0; j < 5; j++) {
            int idx = tid + j * 256;
            int r = idx / 10, c2 = (idx % 10) * 2;
            As[(c2 + 0) * BMP + r] = pf[j].x;
            As[(c2 + 1) * BMP + r] = pf[j].y;
        }
#pragma unroll
        for (int j = 0; j < 5; j++) {
            int bi = tid + j * 256;
            int r = bi >> 6, c2 = (bi & 63) * 2;
            *(float2*)(Bs + r * BN + c2) = pf[5 + j];
        }
        __syncthreads();

        // ---- issue next tile's loads (consumed next iteration) ----
        if (kt + 1 < NKT) {
            const int k0 = (kt + 1) * BK;
#pragma unroll
            for (int j = 0; j < 5; j++) {
                int idx = tid + j * 256;
                int r = idx / 10, c2 = (idx % 10) * 2;
                int gr = row0 + r;
                float2 v = make_float2(0.f, 0.f);
                if (gr < NN) v = *(const float2*)(x + (size_t)gr * F_IN + k0 + c2);
                pf[j] = v;
            }
#pragma unroll
            for (int j = 0; j < 5; j++) {
                int bi = tid + j * 256;
                int r = bi >> 6, c2 = (bi & 63) * 2;
                pf[5 + j] = *(const float2*)(W + (size_t)(k0 + r) * BN + c2);
            }
        }

        // ---- compute current tile ----
#pragma unroll
        for (int kk = 0; kk < BK; kk++) {
            // A fragment: 8 consecutive M-values, 2x LDS.128 (broadcast)
            float4 a0 = *(const float4*)(As + kk * BMP + ty * 8);
            float4 a1 = *(const float4*)(As + kk * BMP + ty * 8 + 4);
            float af[8] = {a0.x, a0.y, a0.z, a0.w, a1.x, a1.y, a1.z, a1.w};
            // B fragment: 8 consecutive N-values, 2x LDS.128
            float4 b0 = *(const float4*)(Bs + kk * BN + tx * 8);
            float4 b1 = *(const float4*)(Bs + kk * BN + tx * 8 + 4);
            unsigned long long bv[4];
            bv[0] = pack2(b0.x, b0.y);
            bv[1] = pack2(b0.z, b0.w);
            bv[2] = pack2(b1.x, b1.y);
            bv[3] = pack2(b1.z, b1.w);
#pragma unroll
            for (int i = 0; i < 8; i++) {
                unsigned long long av = pack2(af[i], af[i]);
#pragma unroll
                for (int j = 0; j < 4; j++) ffma2(acc[i][j], av, bv[j]);
            }
        }
        __syncthreads();
    }

    // ---- fused epilogue: store h1 + attention logits ----
    const int h     = tx >> 1;        // head owned by this lane pair
    const int cbase = (tx & 1) * 8;   // channel offset within head
    float wsrc[8], wdst[8];
#pragma unroll
    for (int j = 0; j < 8; j++) {
        wsrc[j] = att_src[h * C1 + cbase + j];
        wdst[j] = att_dst[h * C1 + cbase + j];
    }

#pragma unroll
    for (int i = 0; i < 8; i++) {
        int gr = row0 + ty * 8 + i;
        float ss = 0.f, sd = 0.f;
        float* o = g_h1 + (size_t)gr * HC + tx * 8;
#pragma unroll
        for (int j = 0; j < 4; j++) {
            float2 v = unpack2(acc[i][j]);
            ss += v.x * wsrc[2 * j] + v.y * wsrc[2 * j + 1];
            sd += v.x * wdst[2 * j] + v.y * wdst[2 * j + 1];
            if (gr < NN) {
                o[j * 2]     = v.x;
                o[j * 2 + 1] = v.y;
            }
        }
        // lane pair (tx, tx^1) == (lane, lane^1): finish head dot product
        ss += __shfl_xor_sync(0xffffffffu, ss, 1);
        sd += __shfl_xor_sync(0xffffffffu, sd, 1);
        if ((tx & 1) == 0 && gr < NN) {
            g_asrc1[gr * H1 + h] = ss;
            g_adst1[gr * H1 + h] = sd;
        }
    }
}

// =====================================================================
// CSR build: scan + scatter (degree histogram fused into k_decode)
// =====================================================================
__global__ void k_scan() {   // single block, 1024 threads
    __shared__ int sums[1024];
    const int t = threadIdx.x;
    const int CH = (NN + 1023) / 1024;
    int base = t * CH;
    int s = 0;
    for (int i = 0; i < CH; i++) {
        int idx = base + i;
        if (idx < NN) s += g_deg[idx];
    }
    sums[t] = s;
    __syncthreads();
    for (int off = 1; off < 1024; off <<= 1) {
        int v = (t >= off) ? sums[t - off] : 0;
        __syncthreads();
        sums[t] += v;
        __syncthreads();
    }
    int run = (t == 0) ? 0 : sums[t - 1];
    for (int i = 0; i < CH; i++) {
        int idx = base + i;
        if (idx < NN) {
            g_offs[idx]   = run;
            g_cursor[idx] = run;
            run += g_deg[idx];
        }
    }
    if (t == 1023) g_offs[NN] = sums[1023];
}

__global__ void k_scatter(int E) {
    int i = blockIdx.x * blockDim.x + threadIdx.x;
    if (i >= E) return;
    int pos = atomicAdd(&g_cursor[g_dst[i]], 1);
    g_csr[pos] = g_src[i];
}

// =====================================================================
// Layer-1 aggregation: warp per dst. Softmax WITHOUT max-shift (exact by
// shift invariance; |logit| <~ 2 for this input distribution, exp stays
// in full fp32 range). Carried chain = 1 FMA per edge; 2-way unroll
// doubles MLP on the csr->h1 gather chain.
// lane l -> head l/4, channels 4l..4l+3. Self-loop handled explicitly.
// =====================================================================
__global__ void k_agg1(const float* __restrict__ b1) {
    int w = (blockIdx.x * blockDim.x + threadIdx.x) >> 5;
    int lane = threadIdx.x & 31;
    if (w >= NN) return;
    const int d  = w;
    const int h  = lane >> 2;
    const int cb = lane * 4;

    const float adst = g_adst1[d * H1 + h];

    // self loop (src = dst)
    float pw0 = __expf(lrelu(g_asrc1[d * H1 + h] + adst));
    float s = pw0;
    float4 hd = *(const float4*)(g_h1 + (size_t)d * HC + cb);
    float4 acc = make_float4(pw0 * hd.x, pw0 * hd.y, pw0 * hd.z, pw0 * hd.w);

    const int beg = g_offs[d], end = g_offs[d + 1];
    int p = beg;
    for (; p + 1 < end; p += 2) {
        int s0 = g_csr[p], s1 = g_csr[p + 1];
        float e0 = lrelu(g_asrc1[s0 * H1 + h] + adst);
        float e1 = lrelu(g_asrc1[s1 * H1 + h] + adst);
        float w0 = __expf(e0), w1 = __expf(e1);
        float4 h0 = *(const float4*)(g_h1 + (size_t)s0 * HC + cb);
        float4 h1v = *(const float4*)(g_h1 + (size_t)s1 * HC + cb);
        acc.x += w0 * h0.x + w1 * h1v.x;
        acc.y += w0 * h0.y + w1 * h1v.y;
        acc.z += w0 * h0.z + w1 * h1v.z;
        acc.w += w0 * h0.w + w1 * h1v.w;
        s += w0 + w1;
    }
    if (p < end) {
        int s0 = g_csr[p];
        float w0 = __expf(lrelu(g_asrc1[s0 * H1 + h] + adst));
        float4 h0 = *(const float4*)(g_h1 + (size_t)s0 * HC + cb);
        acc.x += w0 * h0.x; acc.y += w0 * h0.y;
        acc.z += w0 * h0.z; acc.w += w0 * h0.w;
        s += w0;
    }
    float inv = 1.0f / s;
    float4 bb = *(const float4*)(b1 + cb);
    float4 o;
    o.x = fmaxf(acc.x * inv + bb.x, 0.f);
    o.y = fmaxf(acc.y * inv + bb.y, 0.f);
    o.z = fmaxf(acc.z * inv + bb.z, 0.f);
    o.w = fmaxf(acc.w * inv + bb.w, 0.f);
    *(float4*)(g_out1 + (size_t)d * HC + cb) = o;
}

// =====================================================================
// Layer-2 projection + attention logits: h2 = out1 @ W2 [128,7]
// one thread per node; W2 & att vectors cached in smem (broadcast reads)
// =====================================================================
__global__ void k_proj2(const float* __restrict__ W2,
                        const float* __restrict__ as2,
                        const float* __restrict__ ad2) {
    __shared__ float w[HC * NC];
    __shared__ float ws[NC], wd[NC];
    for (int i = threadIdx.x; i < HC * NC; i += blockDim.x) w[i] = W2[i];
    if (threadIdx.x < NC) {
        ws[threadIdx.x] = as2[threadIdx.x];
        wd[threadIdx.x] = ad2[threadIdx.x];
    }
    __syncthreads();
    int n = blockIdx.x * blockDim.x + threadIdx.x;
    if (n >= NN) return;

    float acc[NC];
#pragma unroll
    for (int c = 0; c < NC; c++) acc[c] = 0.f;
    const float4* xp = (const float4*)(g_out1 + (size_t)n * HC);
#pragma unroll 8
    for (int k4 = 0; k4 < HC / 4; k4++) {
        float4 xv = xp[k4];
        int k = k4 * 4;
#pragma unroll
        for (int c = 0; c < NC; c++) {
            acc[c] += xv.x * w[(k + 0) * NC + c];
            acc[c] += xv.y * w[(k + 1) * NC + c];
            acc[c] += xv.z * w[(k + 2) * NC + c];
            acc[c] += xv.w * w[(k + 3) * NC + c];
        }
    }
    float ss = 0.f, sd = 0.f;
#pragma unroll
    for (int c = 0; c < NC; c++) {
        g_h2[(size_t)n * NC + c] = acc[c];
        ss += acc[c] * ws[c];
        sd += acc[c] * wd[c];
    }
    g_asrc2[n] = ss;
    g_adst2[n] = sd;
}

// =====================================================================
// Layer-2 aggregation: warp per dst, lanes 0..6 hold output channels.
// Same no-shift softmax + 2-way unroll.
// =====================================================================
__global__ void k_agg2(const float* __restrict__ b2, float* __restrict__ out) {
    int w = (blockIdx.x * blockDim.x + threadIdx.x) >> 5;
    int lane = threadIdx.x & 31;
    if (w >= NN) return;
    const int d = w;
    const int c = (lane < NC) ? lane : 0;   // inactive lanes read ch 0 safely

    const float adst = g_adst2[d];

    float pw0 = __expf(lrelu(g_asrc2[d] + adst));
    float s = pw0;
    float acc = pw0 * g_h2[(size_t)d * NC + c];

    const int beg = g_offs[d], end = g_offs[d + 1];
    int p = beg;
    for (; p + 1 < end; p += 2) {
        int s0 = g_csr[p], s1 = g_csr[p + 1];
        float w0 = __expf(lrelu(g_asrc2[s0] + adst));
        float w1 = __expf(lrelu(g_asrc2[s1] + adst));
        float h0 = g_h2[(size_t)s0 * NC + c];
        float h1v = g_h2[(size_t)s1 * NC + c];
        acc += w0 * h0 + w1 * h1v;
        s   += w0 + w1;
    }
    if (p < end) {
        int s0 = g_csr[p];
        float w0 = __expf(lrelu(g_asrc2[s0] + adst));
        acc += w0 * g_h2[(size_t)s0 * NC + c];
        s   += w0;
    }
    if (lane < NC)
        out[(size_t)d * NC + lane] = acc / s + b2[lane];
}

// =====================================================================
// launch
// =====================================================================
extern "C" void kernel_launch(void* const* d_in, const int* in_sizes, int n_in,
                              void* d_out, int out_size) {
    const float* x    = (const float*)d_in[0];
    const void*  ei   = d_in[1];               // int32 or int64, detected on-device
    const float* W1   = (const float*)d_in[2];
    const float* as1  = (const float*)d_in[3];
    const float* ad1  = (const float*)d_in[4];
    const float* b1   = (const float*)d_in[5];
    const float* W2   = (const float*)d_in[6];
    const float* as2  = (const float*)d_in[7];
    const float* ad2  = (const float*)d_in[8];
    const float* b2   = (const float*)d_in[9];
    float*       out  = (float*)d_out;

    const int E = in_sizes[1] / 2;             // element count of [2,E] tensor

    // edge decode (+fused degree histogram) + CSR build
    k_detect<<<1, 32>>>((const int*)ei);
    k_zero<<<(NN + 255) / 256, 256>>>();
    k_decode<<<(E + 255) / 256, 256>>>(ei, E);
    k_scan<<<1, 1024>>>();
    k_scatter<<<(E + 255) / 256, 256>>>(E);

    // layer 1 (attention logits fused into GEMM epilogue)
    k_gemm1<<<(NN + BM - 1) / BM, 256>>>(x, W1, as1, ad1);
    k_agg1<<<(NN * 32 + 255) / 256, 256>>>(b1);

    // layer 2
    k_proj2<<<(NN + 127) / 128, 128>>>(W2, as2, ad2);
    k_agg2<<<(NN * 32 + 255) / 256, 256>>>(b2, out);
}

// round 15
// speedup vs baseline: 1.2478x; 1.2478x over previous
#include <cuda_runtime.h>
#include <cstdint>

// ---------------- problem constants ----------------
#define NN      50000
#define EMAX    800000
#define F_IN    500
#define H1      8
#define C1      16
#define HC      128        // H1*C1
#define NC      7
#define NEG     0.2f
#define NBLK    ((NN + 1023) / 1024)   // 49 scan blocks

// ---------------- device scratch (no allocations allowed) ----------------
// 256B-aligned: these are accessed with float4 loads/stores.
__device__ __align__(256) float g_h1[(size_t)NN * HC];    // layer1 pre-agg features
__device__ __align__(256) float g_out1[(size_t)NN * HC];  // layer1 output (relu+bias)
__device__ float g_asrc1[NN * H1];
__device__ float g_adst1[NN * H1];
__device__ __align__(256) float g_h2[(size_t)NN * NC];
__device__ float g_asrc2[NN];
__device__ float g_adst2[NN];
__device__ int   g_deg[NN];
__device__ int   g_offs[NN + 1];
__device__ int   g_cursor[NN];
__device__ int   g_bsum[64];                   // per-block scan sums
__device__ int   g_csr[EMAX];                  // src node per edge, grouped by dst
__device__ int   g_src[EMAX];                  // decoded edge endpoints
__device__ int   g_dst[EMAX];
__device__ int   g_is64;                       // 1 if edge_index is int64

// ---------------- f32x2 helpers (FFMA2: 2x fp32 throughput, PTX-only) -----
__device__ __forceinline__ unsigned long long pack2(float lo, float hi) {
    unsigned long long r;
    asm("mov.b64 %0, {%1, %2};" : "=l"(r) : "f"(lo), "f"(hi));
    return r;
}
__device__ __forceinline__ void ffma2(unsigned long long& acc,
                                      unsigned long long a,
                                      unsigned long long b) {
    asm("fma.rn.f32x2 %0, %1, %2, %0;" : "+l"(acc) : "l"(a), "l"(b));
}
__device__ __forceinline__ float2 unpack2(unsigned long long v) {
    float lo, hi;
    asm("mov.b64 {%0, %1}, %2;" : "=f"(lo), "=f"(hi) : "l"(v));
    return make_float2(lo, hi);
}

__device__ __forceinline__ float lrelu(float v) {
    return (v > 0.f) ? v : NEG * v;
}

// =====================================================================
// Edge-index dtype detection (int32 vs int64, decided on-device).
// int64 little-endian with node ids < 2^31 => every odd int32 word is 0.
// =====================================================================
__global__ void k_detect(const int* __restrict__ ei32) {
    int lane = threadIdx.x;                 // 32 threads
    int v = ei32[2 * lane + 1];             // odd words of first 64 ints
    unsigned nz = __ballot_sync(0xffffffffu, v != 0);
    if (lane == 0) g_is64 = (nz == 0u) ? 1 : 0;
}

__global__ void k_zero() {
    int i = blockIdx.x * blockDim.x + threadIdx.x;
    if (i < NN) g_deg[i] = 0;
}

// decode + degree histogram fused (g_deg must be zeroed beforehand)
__global__ void k_decode(const void* __restrict__ ei, int E) {
    int i = blockIdx.x * blockDim.x + threadIdx.x;
    if (i >= E) return;
    int s, d;
    if (g_is64) {
        const long long* p = (const long long*)ei;
        s = (int)p[i];
        d = (int)p[E + i];
    } else {
        const int* p = (const int*)ei;
        s = p[i];
        d = p[E + i];
    }
    // clamp: a mis-detection must not trap (finite wrong answer > crash)
    s = min(max(s, 0), NN - 1);
    d = min(max(d, 0), NN - 1);
    g_src[i] = s;
    g_dst[i] = d;
    atomicAdd(&g_deg[d], 1);
}

// =====================================================================
// Multi-block exclusive scan of g_deg -> g_offs / g_cursor.
// (replaces the single-block k_scan that ncu showed at 80.8us, issue=6.7%)
// =====================================================================
__global__ void k_scanA() {     // 49 blocks x 1024: block-local scan
    __shared__ int sums[1024];
    const int t = threadIdx.x;
    const int i = blockIdx.x * 1024 + t;
    int v = (i < NN) ? g_deg[i] : 0;
    sums[t] = v;
    __syncthreads();
    for (int off = 1; off < 1024; off <<= 1) {
        int u = (t >= off) ? sums[t - off] : 0;
        __syncthreads();
        sums[t] += u;
        __syncthreads();
    }
    if (i < NN) g_offs[i] = sums[t] - v;        // exclusive within block
    if (t == 1023) g_bsum[blockIdx.x] = sums[1023];
}

__global__ void k_scanB() {     // 1 block x 64: scan the 49 block sums
    __shared__ int s[64];
    const int t = threadIdx.x;
    int v = (t < NBLK) ? g_bsum[t] : 0;
    s[t] = v;
    __syncthreads();
    for (int off = 1; off < 64; off <<= 1) {
        int u = (t >= off) ? s[t - off] : 0;
        __syncthreads();
        s[t] += u;
        __syncthreads();
    }
    if (t < NBLK) g_bsum[t] = s[t] - v;         // exclusive block base
    if (t == 63) g_offs[NN] = s[63];            // grand total
}

__global__ void k_scanC() {     // add block base, materialize cursor
    int i = blockIdx.x * blockDim.x + threadIdx.x;
    if (i >= NN) return;
    int off = g_offs[i] + g_bsum[i >> 10];
    g_offs[i]   = off;
    g_cursor[i] = off;
}

__global__ void k_scatter(int E) {
    int i = blockIdx.x * blockDim.x + threadIdx.x;
    if (i >= E) return;
    int pos = atomicAdd(&g_cursor[g_dst[i]], 1);
    g_csr[pos] = g_src[i];
}

// =====================================================================
// GEMM1: h1 = x[50000,500] @ W1[500,128]     (fp32, FFMA2 inner loop)
// Block tile 128x128, BK=20, 256 threads, 8x8 per thread; register
// software pipeline; As K-MAJOR; fused attention-logit epilogue.
// =====================================================================
#define BM 128
#define BN 128
#define BK 20
#define BMP 132   // As row stride (K-major): 132*4B = 528B, 16B-aligned rows
#define NKT (F_IN / BK)   // 25 k-tiles

__global__ __launch_bounds__(256, 2)
void k_gemm1(const float* __restrict__ x, const float* __restrict__ W,
             const float* __restrict__ att_src, const float* __restrict__ att_dst) {
    __shared__ __align__(16) float As[BK * BMP];    // [20][132] K-major
    __shared__ __align__(16) float Bs[BK * BN];     // [20][128]

    const int tid = threadIdx.x;
    const int tx = tid & 15;          // 16 col groups * 8 cols
    const int ty = tid >> 4;          // 16 row groups * 8 rows
    const int row0 = blockIdx.x * BM;

    unsigned long long acc[8][4];
#pragma unroll
    for (int i = 0; i < 8; i++)
#pragma unroll
        for (int j = 0; j < 4; j++) acc[i][j] = 0ULL;

    float2 pf[10];                    // prefetch regs: 5x A, 5x B

    // ---- prefetch tile 0 ----
#pragma unroll
    for (int j = 0; j < 5; j++) {
        int idx = tid + j * 256;      // 0..1279 over A tile
        int r = idx / 10, c2 = (idx % 10) * 2;
        int gr = row0 + r;
        float2 v = make_float2(0.f, 0.f);
        if (gr < NN) v = *(const float2*)(x + (size_t)gr * F_IN + c2);
        pf[j] = v;
    }
#pragma unroll
    for (int j = 0; j < 5; j++) {
        int bi = tid + j * 256;       // 0..1279 over B tile
        int r = bi >> 6, c2 = (bi & 63) * 2;
        pf[5 + j] = *(const float2*)(W + (size_t)r * BN + c2);
    }

    for (int kt = 0; kt < NKT; kt++) {
        // ---- store prefetched tile to smem (A transposed to K-major) ----
#pragma unroll
        for (int j = 0; j < 5; j++) {
            int idx = tid + j * 256;
            int r = idx / 10, c2 = (idx % 10) * 2;
            As[(c2 + 0) * BMP + r] = pf[j].x;
            As[(c2 + 1) * BMP + r] = pf[j].y;
        }
#pragma unroll
        for (int j = 0; j < 5; j++) {
            int bi = tid + j * 256;
            int r = bi >> 6, c2 = (bi & 63) * 2;
            *(float2*)(Bs + r * BN + c2) = pf[5 + j];
        }
        __syncthreads();

        // ---- issue next tile's loads (consumed next iteration) ----
        if (kt + 1 < NKT) {
            const int k0 = (kt + 1) * BK;
#pragma unroll
            for (int j = 0; j < 5; j++) {
                int idx = tid + j * 256;
                int r = idx / 10, c2 = (idx % 10) * 2;
                int gr = row0 + r;
                float2 v = make_float2(0.f, 0.f);
                if (gr < NN) v = *(const float2*)(x + (size_t)gr * F_IN + k0 + c2);
                pf[j] = v;
            }
#pragma unroll
            for (int j = 0; j < 5; j++) {
                int bi = tid + j * 256;
                int r = bi >> 6, c2 = (bi & 63) * 2;
                pf[5 + j] = *(const float2*)(W + (size_t)(k0 + r) * BN + c2);
            }
        }

        // ---- compute current tile ----
#pragma unroll
        for (int kk = 0; kk < BK; kk++) {
            // A fragment: 8 consecutive M-values, 2x LDS.128 (broadcast)
            float4 a0 = *(const float4*)(As + kk * BMP + ty * 8);
            float4 a1 = *(const float4*)(As + kk * BMP + ty * 8 + 4);
            float af[8] = {a0.x, a0.y, a0.z, a0.w, a1.x, a1.y, a1.z, a1.w};
            // B fragment: 8 consecutive N-values, 2x LDS.128
            float4 b0 = *(const float4*)(Bs + kk * BN + tx * 8);
            float4 b1 = *(const float4*)(Bs + kk * BN + tx * 8 + 4);
            unsigned long long bv[4];
            bv[0] = pack2(b0.x, b0.y);
            bv[1] = pack2(b0.z, b0.w);
            bv[2] = pack2(b1.x, b1.y);
            bv[3] = pack2(b1.z, b1.w);
#pragma unroll
            for (int i = 0; i < 8; i++) {
                unsigned long long av = pack2(af[i], af[i]);
#pragma unroll
                for (int j = 0; j < 4; j++) ffma2(acc[i][j], av, bv[j]);
            }
        }
        __syncthreads();
    }

    // ---- fused epilogue: store h1 + attention logits ----
    const int h     = tx >> 1;        // head owned by this lane pair
    const int cbase = (tx & 1) * 8;   // channel offset within head
    float wsrc[8], wdst[8];
#pragma unroll
    for (int j = 0; j < 8; j++) {
        wsrc[j] = att_src[h * C1 + cbase + j];
        wdst[j] = att_dst[h * C1 + cbase + j];
    }

#pragma unroll
    for (int i = 0; i < 8; i++) {
        int gr = row0 + ty * 8 + i;
        float ss = 0.f, sd = 0.f;
        float* o = g_h1 + (size_t)gr * HC + tx * 8;
#pragma unroll
        for (int j = 0; j < 4; j++) {
            float2 v = unpack2(acc[i][j]);
            ss += v.x * wsrc[2 * j] + v.y * wsrc[2 * j + 1];
            sd += v.x * wdst[2 * j] + v.y * wdst[2 * j + 1];
            if (gr < NN) {
                o[j * 2]     = v.x;
                o[j * 2 + 1] = v.y;
            }
        }
        // lane pair (tx, tx^1) == (lane, lane^1): finish head dot product
        ss += __shfl_xor_sync(0xffffffffu, ss, 1);
        sd += __shfl_xor_sync(0xffffffffu, sd, 1);
        if ((tx & 1) == 0 && gr < NN) {
            g_asrc1[gr * H1 + h] = ss;
            g_adst1[gr * H1 + h] = sd;
        }
    }
}

// =====================================================================
// Layer-1 aggregation: warp per dst. No-shift softmax (exact: shift
// invariance, |logit| <~ 2). Carried chain = 1 FMA/edge; 2-way unroll.
// =====================================================================
__global__ void k_agg1(const float* __restrict__ b1) {
    int w = (blockIdx.x * blockDim.x + threadIdx.x) >> 5;
    int lane = threadIdx.x & 31;
    if (w >= NN) return;
    const int d  = w;
    const int h  = lane >> 2;
    const int cb = lane * 4;

    const float adst = g_adst1[d * H1 + h];

    // self loop (src = dst)
    float pw0 = __expf(lrelu(g_asrc1[d * H1 + h] + adst));
    float s = pw0;
    float4 hd = *(const float4*)(g_h1 + (size_t)d * HC + cb);
    float4 acc = make_float4(pw0 * hd.x, pw0 * hd.y, pw0 * hd.z, pw0 * hd.w);

    const int beg = g_offs[d], end = g_offs[d + 1];
    int p = beg;
    for (; p + 1 < end; p += 2) {
        int s0 = g_csr[p], s1 = g_csr[p + 1];
        float e0 = lrelu(g_asrc1[s0 * H1 + h] + adst);
        float e1 = lrelu(g_asrc1[s1 * H1 + h] + adst);
        float w0 = __expf(e0), w1 = __expf(e1);
        float4 h0 = *(const float4*)(g_h1 + (size_t)s0 * HC + cb);
        float4 h1v = *(const float4*)(g_h1 + (size_t)s1 * HC + cb);
        acc.x += w0 * h0.x + w1 * h1v.x;
        acc.y += w0 * h0.y + w1 * h1v.y;
        acc.z += w0 * h0.z + w1 * h1v.z;
        acc.w += w0 * h0.w + w1 * h1v.w;
        s += w0 + w1;
    }
    if (p < end) {
        int s0 = g_csr[p];
        float w0 = __expf(lrelu(g_asrc1[s0 * H1 + h] + adst));
        float4 h0 = *(const float4*)(g_h1 + (size_t)s0 * HC + cb);
        acc.x += w0 * h0.x; acc.y += w0 * h0.y;
        acc.z += w0 * h0.z; acc.w += w0 * h0.w;
        s += w0;
    }
    float inv = 1.0f / s;
    float4 bb = *(const float4*)(b1 + cb);
    float4 o;
    o.x = fmaxf(acc.x * inv + bb.x, 0.f);
    o.y = fmaxf(acc.y * inv + bb.y, 0.f);
    o.z = fmaxf(acc.z * inv + bb.z, 0.f);
    o.w = fmaxf(acc.w * inv + bb.w, 0.f);
    *(float4*)(g_out1 + (size_t)d * HC + cb) = o;
}

// =====================================================================
// Layer-2 projection + attention logits: h2 = out1 @ W2 [128,7]
// =====================================================================
__global__ void k_proj2(const float* __restrict__ W2,
                        const float* __restrict__ as2,
                        const float* __restrict__ ad2) {
    __shared__ float w[HC * NC];
    __shared__ float ws[NC], wd[NC];
    for (int i = threadIdx.x; i < HC * NC; i += blockDim.x) w[i] = W2[i];
    if (threadIdx.x < NC) {
        ws[threadIdx.x] = as2[threadIdx.x];
        wd[threadIdx.x] = ad2[threadIdx.x];
    }
    __syncthreads();
    int n = blockIdx.x * blockDim.x + threadIdx.x;
    if (n >= NN) return;

    float acc[NC];
#pragma unroll
    for (int c = 0; c < NC; c++) acc[c] = 0.f;
    const float4* xp = (const float4*)(g_out1 + (size_t)n * HC);
#pragma unroll 8
    for (int k4 = 0; k4 < HC / 4; k4++) {
        float4 xv = xp[k4];
        int k = k4 * 4;
#pragma unroll
        for (int c = 0; c < NC; c++) {
            acc[c] += xv.x * w[(k + 0) * NC + c];
            acc[c] += xv.y * w[(k + 1) * NC + c];
            acc[c] += xv.z * w[(k + 2) * NC + c];
            acc[c] += xv.w * w[(k + 3) * NC + c];
        }
    }
    float ss = 0.f, sd = 0.f;
#pragma unroll
    for (int c = 0; c < NC; c++) {
        g_h2[(size_t)n * NC + c] = acc[c];
        ss += acc[c] * ws[c];
        sd += acc[c] * wd[c];
    }
    g_asrc2[n] = ss;
    g_adst2[n] = sd;
}

// =====================================================================
// Layer-2 aggregation: warp per dst, lanes 0..6 hold output channels.
// =====================================================================
__global__ void k_agg2(const float* __restrict__ b2, float* __restrict__ out) {
    int w = (blockIdx.x * blockDim.x + threadIdx.x) >> 5;
    int lane = threadIdx.x & 31;
    if (w >= NN) return;
    const int d = w;
    const int c = (lane < NC) ? lane : 0;   // inactive lanes read ch 0 safely

    const float adst = g_adst2[d];

    float pw0 = __expf(lrelu(g_asrc2[d] + adst));
    float s = pw0;
    float acc = pw0 * g_h2[(size_t)d * NC + c];

    const int beg = g_offs[d], end = g_offs[d + 1];
    int p = beg;
    for (; p + 1 < end; p += 2) {
        int s0 = g_csr[p], s1 = g_csr[p + 1];
        float w0 = __expf(lrelu(g_asrc2[s0] + adst));
        float w1 = __expf(lrelu(g_asrc2[s1] + adst));
        float h0 = g_h2[(size_t)s0 * NC + c];
        float h1v = g_h2[(size_t)s1 * NC + c];
        acc += w0 * h0 + w1 * h1v;
        s   += w0 + w1;
    }
    if (p < end) {
        int s0 = g_csr[p];
        float w0 = __expf(lrelu(g_asrc2[s0] + adst));
        acc += w0 * g_h2[(size_t)s0 * NC + c];
        s   += w0;
    }
    if (lane < NC)
        out[(size_t)d * NC + lane] = acc / s + b2[lane];
}

// =====================================================================
// launch
// =====================================================================
extern "C" void kernel_launch(void* const* d_in, const int* in_sizes, int n_in,
                              void* d_out, int out_size) {
    const float* x    = (const float*)d_in[0];
    const void*  ei   = d_in[1];               // int32 or int64, detected on-device
    const float* W1   = (const float*)d_in[2];
    const float* as1  = (const float*)d_in[3];
    const float* ad1  = (const float*)d_in[4];
    const float* b1   = (const float*)d_in[5];
    const float* W2   = (const float*)d_in[6];
    const float* as2  = (const float*)d_in[7];
    const float* ad2  = (const float*)d_in[8];
    const float* b2   = (const float*)d_in[9];
    float*       out  = (float*)d_out;

    const int E = in_sizes[1] / 2;             // element count of [2,E] tensor

    // edge decode (+fused degree histogram) + CSR build
    k_detect<<<1, 32>>>((const int*)ei);
    k_zero<<<(NN + 255) / 256, 256>>>();
    k_decode<<<(E + 255) / 256, 256>>>(ei, E);
    k_scanA<<<NBLK, 1024>>>();
    k_scanB<<<1, 64>>>();
    k_scanC<<<(NN + 255) / 256, 256>>>();
    k_scatter<<<(E + 255) / 256, 256>>>(E);

    // layer 1 (attention logits fused into GEMM epilogue)
    k_gemm1<<<(NN + BM - 1) / BM, 256>>>(x, W1, as1, ad1);
    k_agg1<<<(NN * 32 + 255) / 256, 256>>>(b1);

    // layer 2
    k_proj2<<<(NN + 127) / 128, 128>>>(W2, as2, ad2);
    k_agg2<<<(NN * 32 + 255) / 256, 256>>>(b2, out);
}